// round 1
// baseline (speedup 1.0000x reference)
#include <cuda_runtime.h>

#define BATCH 4
#define HEADS 6
#define NG 24            // BATCH*HEADS groups
#define NS 1024          // sequence length (32*32)
#define DH 64            // dim head
#define CD 384           // channel dim
#define NN (NS*NS)       // 1048576
#define KTOP 734003      // int(0.7 * 1024*1024)
#define SCALE 0.125f

// Output packing (tuple order, fp32, flattened):
#define OFF_PROJ 0
#define OFF_MAP  1572864
#define OFF_CAUS 1576960
#define OFF_NONC 26742784
#define OFF_MASK 51908608

// ---- scratch (static device arrays; no allocations) ----
__device__ float g_q[NG*NS*DH];     // [g][n][d]
__device__ float g_k[NG*DH*NS];     // [g][d][m]
__device__ float g_v[NG*NS*DH];     // [g][m][d]
__device__ float g_o[BATCH*CD*NS];  // [b][i][n], i = h*64+d
__device__ unsigned int       g_hist[NG*8192];
__device__ unsigned long long g_prefix[NG];
__device__ unsigned int       g_krem[NG];

// ---------------------------------------------------------------------------
__global__ void init_kernel(float* out) {
    int t = blockIdx.x * blockDim.x + threadIdx.x;
    if (t < NG*8192) g_hist[t] = 0u;
    if (t < BATCH*NS) out[OFF_MAP + t] = 0.f;
    if (t < NG) { g_prefix[t] = 0ull; g_krem[t] = (unsigned)KTOP; }
}

// ---------------------------------------------------------------------------
// QKV projections: O[o,n] = sum_c W[o,c] * X[c,n] per batch, 64x64 tiles.
__global__ void proj_kernel(const float* __restrict__ qin,
                            const float* __restrict__ cin,
                            const float* __restrict__ Wq,
                            const float* __restrict__ Wk,
                            const float* __restrict__ Wv) {
    __shared__ float ws[64][65];
    __shared__ float xs[64][64];
    int which = blockIdx.z;               // 0=q (from query), 1=k, 2=v (from context)
    int b = blockIdx.y;
    int otile = (blockIdx.x >> 4) * 64;   // 6 o-tiles
    int ntile = (blockIdx.x & 15) * 64;   // 16 n-tiles
    const float* W = (which == 0) ? Wq : (which == 1 ? Wk : Wv);
    const float* X = ((which == 0) ? qin : cin) + b * CD * NS;
    int t = threadIdx.x;
    int tx = t & 15, ty = t >> 4;
    float acc[4][4];
    #pragma unroll
    for (int r = 0; r < 4; r++)
        #pragma unroll
        for (int c = 0; c < 4; c++) acc[r][c] = 0.f;

    for (int ct = 0; ct < CD; ct += 64) {
        #pragma unroll
        for (int i = 0; i < 16; i++) {
            int idx = t + i * 256;
            int r = idx >> 6, c = idx & 63;
            ws[r][c] = W[(otile + r) * CD + ct + c];
            xs[r][c] = X[(ct + r) * NS + ntile + c];
        }
        __syncthreads();
        #pragma unroll 8
        for (int c = 0; c < 64; c++) {
            float4 xv = *(const float4*)&xs[c][tx << 2];
            #pragma unroll
            for (int r = 0; r < 4; r++) {
                float wv = ws[ty * 4 + r][c];
                acc[r][0] = fmaf(wv, xv.x, acc[r][0]);
                acc[r][1] = fmaf(wv, xv.y, acc[r][1]);
                acc[r][2] = fmaf(wv, xv.z, acc[r][2]);
                acc[r][3] = fmaf(wv, xv.w, acc[r][3]);
            }
        }
        __syncthreads();
    }
    #pragma unroll
    for (int r = 0; r < 4; r++) {
        int o = otile + ty * 4 + r;
        int h = o >> 6, d = o & 63;
        #pragma unroll
        for (int cc = 0; cc < 4; cc++) {
            int n = ntile + tx * 4 + cc;
            float val = acc[r][cc];
            if (which == 1)      g_k[((b*HEADS + h) * DH + d) * NS + n] = val;
            else if (which == 0) g_q[((b*HEADS + h) * NS + n) * DH + d] = val;
            else                 g_v[((b*HEADS + h) * NS + n) * DH + d] = val;
        }
    }
}

// ---------------------------------------------------------------------------
// scores + softmax: block computes 16 query rows x full 1024 keys for one group,
// writes softmax probabilities straight into the attn_causal region.
__global__ void attn_kernel(float* __restrict__ attn) {
    __shared__ float qs[16][64];
    __shared__ float ks[64][64];
    int g = blockIdx.y;
    int n0 = blockIdx.x * 16;
    int t = threadIdx.x;
    int lane = t & 15, row = t >> 4;

    #pragma unroll
    for (int i = 0; i < 4; i++) {
        int idx = t + i * 256;
        int r = idx >> 6, d = idx & 63;
        qs[r][d] = g_q[(g * NS + n0 + r) * DH + d];
    }

    float acc[64];
    #pragma unroll
    for (int i = 0; i < 64; i++) acc[i] = 0.f;

    #pragma unroll
    for (int j = 0; j < 16; j++) {
        __syncthreads();
        #pragma unroll
        for (int i = 0; i < 16; i++) {
            int idx = t + i * 256;
            int d = idx >> 6, m = idx & 63;
            ks[d][m] = g_k[(g * DH + d) * NS + j * 64 + m];
        }
        __syncthreads();
        #pragma unroll 8
        for (int d = 0; d < 64; d++) {
            float qv = qs[row][d];
            float4 kv = *(const float4*)&ks[d][lane << 2];
            acc[4*j+0] = fmaf(qv, kv.x, acc[4*j+0]);
            acc[4*j+1] = fmaf(qv, kv.y, acc[4*j+1]);
            acc[4*j+2] = fmaf(qv, kv.z, acc[4*j+2]);
            acc[4*j+3] = fmaf(qv, kv.w, acc[4*j+3]);
        }
    }

    // softmax over the 1024 columns of this row (16 lanes hold 64 each)
    float mx = -1e30f;
    #pragma unroll
    for (int i = 0; i < 64; i++) { acc[i] *= SCALE; mx = fmaxf(mx, acc[i]); }
    #pragma unroll
    for (int off = 8; off >= 1; off >>= 1)
        mx = fmaxf(mx, __shfl_xor_sync(0xffffffffu, mx, off));
    float sum = 0.f;
    #pragma unroll
    for (int i = 0; i < 64; i++) { acc[i] = expf(acc[i] - mx); sum += acc[i]; }
    #pragma unroll
    for (int off = 8; off >= 1; off >>= 1)
        sum += __shfl_xor_sync(0xffffffffu, sum, off);
    float inv = 1.0f / sum;

    size_t base = (size_t)g * NN + (size_t)(n0 + row) * NS;
    #pragma unroll
    for (int j = 0; j < 16; j++) {
        float4 v4 = make_float4(acc[4*j]*inv, acc[4*j+1]*inv, acc[4*j+2]*inv, acc[4*j+3]*inv);
        *(float4*)&attn[base + j * 64 + (lane << 2)] = v4;
    }
}

// ---------------------------------------------------------------------------
// Radix-select pass: histogram of 13 key bits among candidates matching prefix.
// key = (float_bits(v) << 20) | (2^20-1 - idx)  -- 52-bit, unique, encodes
// jax top_k's (value desc, index asc) ordering exactly.
__global__ void hist_kernel(const float* __restrict__ attn, int shift) {
    __shared__ unsigned int hist[8192];
    int g = blockIdx.y;
    int t = threadIdx.x;
    for (int i = t; i < 8192; i += 256) hist[i] = 0u;
    __syncthreads();
    unsigned long long pref = g_prefix[g];
    size_t gbase = (size_t)g * NN;
    int base = blockIdx.x * 65536;
    for (int i = t; i < 65536; i += 256) {
        int idx = base + i;
        float v = attn[gbase + idx];
        unsigned long long key =
            ((unsigned long long)__float_as_uint(v) << 20) |
            (unsigned long long)(1048575 - idx);
        if ((key >> (shift + 13)) == pref)
            atomicAdd(&hist[(unsigned)((key >> shift) & 8191)], 1u);
    }
    __syncthreads();
    for (int i = t; i < 8192; i += 256)
        if (hist[i]) atomicAdd(&g_hist[g * 8192 + i], hist[i]);
}

// Find the bin containing the k-th largest, update prefix/kremain, zero hist.
__global__ void scan_kernel() {
    __shared__ unsigned int ssum[256];
    int g = blockIdx.x;
    int t = threadIdx.x;
    unsigned int* h = &g_hist[g * 8192];
    int hi = 8191 - t * 32;               // descending 32-bin chunk per thread
    unsigned int mysum = 0;
    #pragma unroll
    for (int k = 0; k < 32; k++) mysum += h[hi - k];
    ssum[t] = mysum;
    __syncthreads();
    for (int off = 1; off < 256; off <<= 1) {
        unsigned int v = (t >= off) ? ssum[t - off] : 0u;
        __syncthreads();
        ssum[t] += v;
        __syncthreads();
    }
    unsigned int incl = ssum[t];
    unsigned int excl = incl - mysum;
    unsigned int kr = g_krem[g];
    if (excl < kr && kr <= incl) {
        unsigned int cum = excl;
        for (int k = 0; k < 32; k++) {
            int bin = hi - k;
            unsigned int c = h[bin];
            if (cum + c >= kr) {
                g_prefix[g] = (g_prefix[g] << 13) | (unsigned long long)bin;
                g_krem[g] = kr - cum;
                break;
            }
            cum += c;
        }
    }
    __syncthreads();
    for (int i = t; i < 8192; i += 256) h[i] = 0u;   // ready for next pass/replay
}

// ---------------------------------------------------------------------------
// out[n,d] = sum_m attn[n,m] * v[m,d]; store to g_o as [b][h*64+d][n]
__global__ void av_kernel(const float* __restrict__ attn) {
    __shared__ float as_[16][64];
    __shared__ float vs[64][64];
    int g = blockIdx.y;
    int b = g / HEADS, h = g % HEADS;
    int n0 = blockIdx.x * 16;
    int t = threadIdx.x;
    int dg = t & 15, row = t >> 4;
    float4 acc = make_float4(0.f, 0.f, 0.f, 0.f);
    for (int j = 0; j < 16; j++) {
        __syncthreads();
        #pragma unroll
        for (int i = 0; i < 4; i++) {
            int idx = t + i * 256;
            int r = idx >> 6, m = idx & 63;
            as_[r][m] = attn[(size_t)g * NN + (size_t)(n0 + r) * NS + j * 64 + m];
        }
        #pragma unroll
        for (int i = 0; i < 16; i++) {
            int idx = t + i * 256;
            int m = idx >> 6, d = idx & 63;
            vs[m][d] = g_v[(g * NS + j * 64 + m) * DH + d];
        }
        __syncthreads();
        #pragma unroll 8
        for (int m = 0; m < 64; m++) {
            float av = as_[row][m];
            float4 vv = *(const float4*)&vs[m][dg << 2];
            acc.x = fmaf(av, vv.x, acc.x);
            acc.y = fmaf(av, vv.y, acc.y);
            acc.z = fmaf(av, vv.z, acc.z);
            acc.w = fmaf(av, vv.w, acc.w);
        }
    }
    int n = n0 + row;
    int ib = h * 64 + dg * 4;
    g_o[(b * CD + ib + 0) * NS + n] = acc.x;
    g_o[(b * CD + ib + 1) * NS + n] = acc.y;
    g_o[(b * CD + ib + 2) * NS + n] = acc.z;
    g_o[(b * CD + ib + 3) * NS + n] = acc.w;
}

// ---------------------------------------------------------------------------
// out_proj = Wo @ g_o + bo
__global__ void oproj_kernel(const float* __restrict__ Wo,
                             const float* __restrict__ bo,
                             float* __restrict__ out) {
    __shared__ float ws[64][65];
    __shared__ float xs[64][64];
    int b = blockIdx.y;
    int otile = (blockIdx.x >> 4) * 64;
    int ntile = (blockIdx.x & 15) * 64;
    const float* X = g_o + b * CD * NS;
    int t = threadIdx.x;
    int tx = t & 15, ty = t >> 4;
    float acc[4][4];
    #pragma unroll
    for (int r = 0; r < 4; r++)
        #pragma unroll
        for (int c = 0; c < 4; c++) acc[r][c] = 0.f;
    for (int ct = 0; ct < CD; ct += 64) {
        #pragma unroll
        for (int i = 0; i < 16; i++) {
            int idx = t + i * 256;
            int r = idx >> 6, c = idx & 63;
            ws[r][c] = Wo[(otile + r) * CD + ct + c];
            xs[r][c] = X[(ct + r) * NS + ntile + c];
        }
        __syncthreads();
        #pragma unroll 8
        for (int c = 0; c < 64; c++) {
            float4 xv = *(const float4*)&xs[c][tx << 2];
            #pragma unroll
            for (int r = 0; r < 4; r++) {
                float wv = ws[ty * 4 + r][c];
                acc[r][0] = fmaf(wv, xv.x, acc[r][0]);
                acc[r][1] = fmaf(wv, xv.y, acc[r][1]);
                acc[r][2] = fmaf(wv, xv.z, acc[r][2]);
                acc[r][3] = fmaf(wv, xv.w, acc[r][3]);
            }
        }
        __syncthreads();
    }
    #pragma unroll
    for (int r = 0; r < 4; r++) {
        int o = otile + ty * 4 + r;
        float bias = bo[o];
        #pragma unroll
        for (int cc = 0; cc < 4; cc++)
            out[((size_t)b * CD + o) * NS + ntile + tx * 4 + cc] = acc[r][cc] + bias;
    }
}

// ---------------------------------------------------------------------------
// final: split attn into causal/noncausal/mask via threshold key, accumulate
// attn_map column means.
__global__ void mask_kernel(float* __restrict__ out) {
    __shared__ float colsum[1024];
    int g = blockIdx.y;
    int b = g / HEADS;
    unsigned long long thr = g_prefix[g];
    int t = threadIdx.x;
    #pragma unroll
    for (int cc = 0; cc < 4; cc++) colsum[t + cc * 256] = 0.f;
    __syncthreads();
    float* caus = out + OFF_CAUS;
    float* nonc = out + OFF_NONC;
    float* mask = out + OFF_MASK;
    size_t gbase = (size_t)g * NN;
    for (int r = 0; r < 8; r++) {
        int n = blockIdx.x * 8 + r;
        int rowoff = n * NS;
        #pragma unroll
        for (int cc = 0; cc < 4; cc++) {
            int col = t + cc * 256;
            int idx = rowoff + col;
            float v = caus[gbase + idx];
            unsigned long long key =
                ((unsigned long long)__float_as_uint(v) << 20) |
                (unsigned long long)(1048575 - idx);
            bool sel = (key >= thr);
            caus[gbase + idx] = sel ? v : 0.f;
            nonc[gbase + idx] = sel ? 0.f : v;
            mask[gbase + idx] = sel ? 1.f : 0.f;
            colsum[col] += v;
        }
    }
    __syncthreads();
    #pragma unroll
    for (int cc = 0; cc < 4; cc++) {
        int col = t + cc * 256;
        atomicAdd(&out[OFF_MAP + b * NS + col], colsum[col] * (1.f / 6144.f));
    }
}

// ---------------------------------------------------------------------------
extern "C" void kernel_launch(void* const* d_in, const int* in_sizes, int n_in,
                              void* d_out, int out_size) {
    const float* query   = (const float*)d_in[0];
    const float* context = (const float*)d_in[1];
    const float* Wq      = (const float*)d_in[2];
    const float* Wk      = (const float*)d_in[3];
    const float* Wv      = (const float*)d_in[4];
    const float* Wo      = (const float*)d_in[5];
    const float* bo      = (const float*)d_in[6];
    float* out = (float*)d_out;
    float* attn = out + OFF_CAUS;   // softmax scratch lives in causal slot

    init_kernel<<<768, 256>>>(out);
    proj_kernel<<<dim3(96, 4, 3), 256>>>(query, context, Wq, Wk, Wv);
    attn_kernel<<<dim3(64, NG), 256>>>(attn);
    for (int p = 0; p < 4; p++) {
        int shift = 39 - 13 * p;
        hist_kernel<<<dim3(16, NG), 256>>>(attn, shift);
        scan_kernel<<<NG, 256>>>();
    }
    av_kernel<<<dim3(64, NG), 256>>>(attn);
    oproj_kernel<<<dim3(96, 4), 256>>>(Wo, bo, out);
    mask_kernel<<<dim3(128, NG), 256>>>(out);
}